// round 7
// baseline (speedup 1.0000x reference)
#include <cuda_runtime.h>
#include <climits>

// Fixed problem shape: B=8, C=1, H=W=768.
#define BB    8
#define HH    768
#define WW    768
#define HWSZ  (HH * WW)          // 589824
#define NTOT  (BB * HWSZ)        // 4718592
#define N4    (NTOT / 4)         // 1179648
#define NW    (NTOT / 32)        // 147456 bitmap words per mask

#define TS        32
#define TILES_X   24
#define TILES_Y   24

#define EPT   (23 * 768)         // per-image boundary edges, one orientation
#define EPI   (2 * EPT)          // 35328
#define NEDGE (BB * EPI)         // 282624 (one thread = one edge, both masks)

#define BG16  0xFFFFu
#define LOSS_BLOCKS (N4 / 256)   // 4608, exact cover

// Scratch (static __device__ arrays; allocation-free kernel_launch).
__device__ unsigned g_loc[NTOT];    // packed tile-local roots: pred | (targ<<16)
__device__ int      g_parp[NTOT];   // pred UF parents (tile-root entries only)
__device__ int      g_part[NTOT];   // target UF parents (tile-root entries only)
__device__ int2     g_mm[NTOT];     // {min,max} targ root per pred root (root entries)
__device__ unsigned g_bmp[2][NW];   // root bitmaps: [mask][word]
__device__ int      g_flag;         // rescale flag (published fresh each run)
__device__ int      g_neg, g_ctrf;  // k_flag state (zero-init, self-reset)
__device__ int      g_ctr;          // k_loss last-block counter (self-reset)
__device__ double   g_psum[LOSS_BLOCKS];

// Exact reference arithmetic for (x + 1.0) * 0.5 without FMA contraction.
__device__ __forceinline__ float resc01(float x) {
    return __fmul_rn(__fadd_rn(x, 1.0f), 0.5f);
}

// ---------------------------------------------------------------------------
// Union-find (min-index rooting; parent <= child invariant)
// ---------------------------------------------------------------------------
__device__ __forceinline__ int uf_find(const int* L, int x) {
    int p = L[x];
    while (p != x) { x = p; p = L[x]; }
    return x;
}

__device__ __forceinline__ int uf_findc(int* L, int x) {   // find + compress
    int r = x, p = L[r];
    while (p != r) { r = p; p = L[r]; }
    while (L[x] != r) { int nx = L[x]; L[x] = r; x = nx; }
    return r;
}

__device__ __forceinline__ void uf_union(int* L, int a, int b) {
    int ra = uf_find(L, a);
    int rb = uf_find(L, b);
    while (ra != rb) {
        int hi = ra > rb ? ra : rb;
        int lo = ra > rb ? rb : ra;
        int old = atomicMin(&L[hi], lo);
        if (old == hi) break;
        ra = lo;
        rb = old;
    }
}

// Shared-memory union-find.
__device__ __forceinline__ int s_find(const int* L, int x) {
    int p = L[x];
    while (p != x) { x = p; p = L[x]; }
    return x;
}

__device__ __forceinline__ void s_union(int* L, int a, int b) {
    int ra = s_find(L, a);
    int rb = s_find(L, b);
    while (ra != rb) {
        int hi = ra > rb ? ra : rb;
        int lo = ra > rb ? rb : ra;
        int old = atomicMin(&L[hi], lo);
        if (old == hi) break;
        ra = lo;
        rb = old;
    }
}

// Reconstruct global index of a tile-local root. (ty, tx) = tile-origin coords.
__device__ __forceinline__ int rec_root(int base, unsigned loc) {
    return base + (int)(loc >> 5) * WW + (int)(loc & 31u);
}

// ---------------------------------------------------------------------------
// Kernels
// ---------------------------------------------------------------------------
// Publish the rescale flag fresh each run (last-block pattern; self-resetting).
__global__ void k_flag(const float4* __restrict__ pred) {
    int i = blockIdx.x * blockDim.x + threadIdx.x;
    float4 v = pred[i];
    bool neg = (v.x < 0.f) | (v.y < 0.f) | (v.z < 0.f) | (v.w < 0.f);
    bool bneg = __syncthreads_or(neg);
    __shared__ bool last;
    if (threadIdx.x == 0) {
        if (bneg) atomicOr(&g_neg, 1);
        __threadfence();
        last = (atomicAdd(&g_ctrf, 1) == (int)gridDim.x - 1);
    }
    __syncthreads();
    if (last && threadIdx.x == 0) { g_flag = g_neg; g_neg = 0; g_ctrf = 0; }
}

// Per 32x32 tile: masks, in-tile CCL in smem, packed 16-bit labels, root
// bitmaps, UF-parent + g_mm init at tile-root pixels only.
__global__ void k_tile(const float* __restrict__ pred,
                       const float* __restrict__ target) {
    __shared__ int lp[TS * TS];
    __shared__ int lt[TS * TS];
    int lx = threadIdx.x, ly = threadIdx.y;
    int l  = ly * TS + lx;
    int gx = blockIdx.x * TS + lx;
    int gy = blockIdx.y * TS + ly;
    int b  = blockIdx.z;
    int gi = b * HWSZ + gy * WW + gx;

    bool  resc = (g_flag != 0);
    float p = pred[gi];
    float t = target[gi];
    float pp  = resc ? resc01(p) : p;
    float t01 = resc01(t);
    bool mp = pp  > 0.5f;
    bool mt = t01 > 0.5f;

    lp[l] = mp ? l : -1;
    lt[l] = mt ? l : -1;
    __syncthreads();

    if (mp) {
        if (lx > 0 && lp[l - 1]  >= 0) s_union(lp, l, l - 1);
        if (ly > 0 && lp[l - TS] >= 0) s_union(lp, l, l - TS);
    }
    if (mt) {
        if (lx > 0 && lt[l - 1]  >= 0) s_union(lt, l, l - 1);
        if (ly > 0 && lt[l - TS] >= 0) s_union(lt, l, l - TS);
    }
    __syncthreads();

    unsigned rp16 = BG16, rt16 = BG16;
    bool proot = false, troot = false;
    if (mp) {
        int r = s_find(lp, l);
        rp16 = (unsigned)r;
        if (r == l) {
            proot = true;
            g_parp[gi] = gi;
            g_mm[gi]   = make_int2(INT_MAX, -1);
        }
    }
    if (mt) {
        int r = s_find(lt, l);
        rt16 = (unsigned)r;
        if (r == l) { troot = true; g_part[gi] = gi; }
    }
    g_loc[gi] = rp16 | (rt16 << 16);

    // Root bitmaps: one word per warp-row (gi of lane 0 is 32-aligned).
    unsigned bp = __ballot_sync(0xffffffffu, proot);
    unsigned bt = __ballot_sync(0xffffffffu, troot);
    if (lx == 0) {
        int w = (gi >> 5);
        g_bmp[0][w] = bp;    // unconditional: overwrite stale replay data
        g_bmp[1][w] = bt;
    }
}

// Merge across tile boundaries; one thread = one edge, handles both masks.
__global__ void k_bmerge() {
    int tid = blockIdx.x * blockDim.x + threadIdx.x;
    if (tid >= NEDGE) return;
    int b = tid / EPI;
    int e = tid % EPI;
    int y, x, ny, nx;
    if (e < EPT) {                       // vertical boundary: (y,x)-(y,x-1)
        int bi = e / HH; y = e % HH;
        x = TS * (bi + 1); ny = y; nx = x - 1;
    } else {                             // horizontal boundary: (y,x)-(y-1,x)
        e -= EPT;
        int bi = e / WW; x = e % WW;
        y = TS * (bi + 1); ny = y - 1; nx = x;
    }
    int idx = b * HWSZ + y * WW + x;
    int n   = b * HWSZ + ny * WW + nx;
    unsigned a = g_loc[idx], c = g_loc[n];
    int abase = b * HWSZ + (y  & ~31) * WW + (x  & ~31);
    int cbase = b * HWSZ + (ny & ~31) * WW + (nx & ~31);

    if ((a & BG16) != BG16 && (c & BG16) != BG16)
        uf_union(g_parp, rec_root(abase, a & BG16), rec_root(cbase, c & BG16));
    if ((a >> 16) != BG16 && (c >> 16) != BG16)
        uf_union(g_part, rec_root(abase, a >> 16), rec_root(cbase, c >> 16));
}

// Flatten every tile-root entry to its final root (bitmap-driven; ~600K roots,
// whole working set L2-resident). After this, par[tile_root] == final root.
__global__ void k_compress() {
    int tid = blockIdx.x * blockDim.x + threadIdx.x;   // covers 2*NW exactly
    int m = tid >= NW;
    int w = m ? tid - NW : tid;
    unsigned bits = g_bmp[m][w];
    int* L = m ? g_part : g_parp;
    int base = w << 5;
    while (bits) {
        int bit = __ffs(bits) - 1;
        bits &= bits - 1;
        uf_findc(L, base + bit);
    }
}

// Per overlap pixel: 1-hop root resolution + warp-grouped min/max atomics.
__global__ void k_agg() {
    int i = blockIdx.x * blockDim.x + threadIdx.x;   // exact cover of NTOT
    int lane = threadIdx.x & 31;
    unsigned v = g_loc[i];
    unsigned pl = v & BG16, tl = v >> 16;
    bool pair = (pl != BG16) && (tl != BG16);
    int rp = -1, rt = -1;
    if (pair) {
        int rem  = i % HWSZ;
        int base = (i - rem) + ((rem / WW) & ~31) * WW + ((rem % WW) & ~31);
        rp = g_parp[rec_root(base, pl)];   // 1 hop: entry already flattened
        rt = g_part[rec_root(base, tl)];
    }
    unsigned valid = __ballot_sync(0xffffffffu, pair);
    if (pair) {
        unsigned grp = __match_any_sync(valid, rp);
        int mn = rt, mx = rt;
        unsigned rest = grp & ~(1u << lane);
        while (rest) {
            int src = __ffs(rest) - 1;
            rest &= rest - 1;
            int o = __shfl_sync(grp, rt, src);
            mn = min(mn, o);
            mx = max(mx, o);
        }
        if (lane == __ffs(grp) - 1) {
            atomicMin(&g_mm[rp].x, mn);
            atomicMax(&g_mm[rp].y, mx);
        }
    }
}

// Weighted loss + fused deterministic final reduction (last-block pattern).
__global__ void k_loss(const float4* __restrict__ pred,
                       const float4* __restrict__ target,
                       float* __restrict__ out) {
    __shared__ double sh[256];
    bool resc = (g_flag != 0);
    int v = blockIdx.x * blockDim.x + threadIdx.x;   // exact cover of N4
    int i0  = 4 * v;
    int rem  = i0 % HWSZ;
    int base = (i0 - rem) + ((rem / WW) & ~31) * WW + ((rem % WW) & ~31);
    // all 4 pixels lie in the same tile row (x0 % 4 == 0, tiles 32-wide)

    float4 p = pred[v];
    float4 t = target[v];
    uint4  L = ((const uint4*)g_loc)[v];
    float pv[4] = {p.x, p.y, p.z, p.w};
    float tv[4] = {t.x, t.y, t.z, t.w};
    unsigned lv[4] = {L.x, L.y, L.z, L.w};

    double s = 0.0;
    #pragma unroll
    for (int j = 0; j < 4; j++) {
        float pp  = resc ? resc01(pv[j]) : pv[j];
        float t01 = resc01(tv[j]);
        float pl  = fabsf(pp - t01);
        float w   = 1.0f;
        unsigned lr = lv[j] & BG16;
        if (lr != BG16 && !(t01 > 0.5f)) {      // pred fg, target bg
            int r = g_parp[rec_root(base, lr)];  // 1 hop (L2-resident)
            int2 mm = g_mm[r];
            if (mm.y > mm.x) w = 11.0f;          // merged component
        }
        s += (double)(pl * w);
    }

    sh[threadIdx.x] = s;
    __syncthreads();
    for (int off = 128; off > 0; off >>= 1) {
        if (threadIdx.x < off) sh[threadIdx.x] += sh[threadIdx.x + off];
        __syncthreads();
    }
    __shared__ bool last;
    if (threadIdx.x == 0) {
        g_psum[blockIdx.x] = sh[0];
        __threadfence();
        last = (atomicAdd(&g_ctr, 1) == (int)gridDim.x - 1);
    }
    __syncthreads();

    if (last) {
        double s2 = 0.0;
        for (int k = 0; k < LOSS_BLOCKS / 256; k++)          // fixed order
            s2 += g_psum[threadIdx.x + 256 * k];
        sh[threadIdx.x] = s2;
        __syncthreads();
        for (int off = 128; off > 0; off >>= 1) {
            if (threadIdx.x < off) sh[threadIdx.x] += sh[threadIdx.x + off];
            __syncthreads();
        }
        if (threadIdx.x == 0) {
            out[0] = (float)(sh[0] / (double)NTOT);
            g_ctr = 0;                                       // reset for replay
        }
    }
}

// ---------------------------------------------------------------------------
extern "C" void kernel_launch(void* const* d_in, const int* in_sizes, int n_in,
                              void* d_out, int out_size) {
    const float* pred   = (const float*)d_in[0];
    const float* target = (const float*)d_in[1];
    float* out = (float*)d_out;

    k_flag<<<N4 / 256, 256>>>((const float4*)pred);
    k_tile<<<dim3(TILES_X, TILES_Y, BB), dim3(TS, TS)>>>(pred, target);
    k_bmerge<<<(NEDGE + 255) / 256, 256>>>();
    k_compress<<<(2 * NW) / 256, 256>>>();
    k_agg<<<NTOT / 256, 256>>>();
    k_loss<<<LOSS_BLOCKS, 256>>>((const float4*)pred, (const float4*)target, out);
}